// round 1
// baseline (speedup 1.0000x reference)
#include <cuda_runtime.h>
#include <cstdint>

#define BATCH   16
#define NPTS    8192
#define NPOINT  2048
#define KNN     16
#define CIN     64
#define COUT    128

// ---------------- scratch (device globals; no allocation) ----------------
__device__ float g_h[BATCH * NPTS * COUT];     // conv output (no bias), 64 MB
__device__ int   g_fps[BATCH * NPOINT];        // FPS indices
__device__ float g_sum[COUT];
__device__ float g_sq[COUT];
__device__ float g_scale[COUT];
__device__ float g_shift[COUT];

// ---------------- kernel 1: zero accumulators (replay-safe) ----------------
__global__ void zero_kernel() {
    int t = threadIdx.x;
    if (t < COUT) { g_sum[t] = 0.f; g_sq[t] = 0.f; }
}

// ---------------- kernel 2: fused FPS (blocks 0..15) + GEMM (blocks 16..) ----------------
// FPS: 512 threads, 16 points/thread, coords+dist in registers.
// GEMM: 128-row x 128-col tile per block, K=64, smem tiles padded to 65.
#define FPS_T 512
#define PPT   16

__global__ __launch_bounds__(512) void fps_gemm_kernel(
    const float* __restrict__ xyz,
    const float* __restrict__ feat,
    const float* __restrict__ Wm)
{
    extern __shared__ float smem[];
    int tid = threadIdx.x;

    if (blockIdx.x < BATCH) {
        // ---------------- FPS ----------------
        int b = blockIdx.x;
        const float* base = xyz + (size_t)b * NPTS * 3;
        float px[PPT], py[PPT], pz[PPT], dist[PPT];
#pragma unroll
        for (int i = 0; i < PPT; i++) {
            int p = i * FPS_T + tid;
            px[i] = base[p * 3 + 0];
            py[i] = base[p * 3 + 1];
            pz[i] = base[p * 3 + 2];
            dist[i] = 1e10f;
        }
        float* sWarp = smem;               // [16]
        float* sBest = smem + 16;          // [1]
        int*   sWin  = (int*)(smem + 17);  // [1]
        float* sC    = smem + 18;          // [3]
        if (tid == 0) {
            sC[0] = px[0]; sC[1] = py[0]; sC[2] = pz[0];
            g_fps[b * NPOINT] = 0;
        }
        __syncthreads();
        int lane = tid & 31, wid = tid >> 5;

        for (int t = 1; t < NPOINT; t++) {
            float cx = sC[0], cy = sC[1], cz = sC[2];
            float lb = -1.f;
#pragma unroll
            for (int i = 0; i < PPT; i++) {
                float dx = px[i] - cx, dy = py[i] - cy, dz = pz[i] - cz;
                float d  = fmaf(dx, dx, fmaf(dy, dy, dz * dz));
                float nd = fminf(dist[i], d);
                dist[i] = nd;
                lb = fmaxf(lb, nd);
            }
            float wm = lb;
#pragma unroll
            for (int off = 16; off; off >>= 1)
                wm = fmaxf(wm, __shfl_xor_sync(0xffffffffu, wm, off));
            if (lane == 0) sWarp[wid] = wm;
            __syncthreads();
            if (tid < 32) {
                float v = (tid < 16) ? sWarp[tid] : -1.f;
#pragma unroll
                for (int off = 8; off; off >>= 1)
                    v = fmaxf(v, __shfl_xor_sync(0xffffffffu, v, off));
                if (tid == 0) { *sBest = v; *sWin = 0x7fffffff; }
            }
            __syncthreads();
            float gb = *sBest;
            if (lb == gb) {
                int ci = 0x7fffffff;
#pragma unroll
                for (int i = PPT - 1; i >= 0; i--)
                    if (dist[i] == gb) ci = i * FPS_T + tid;  // smallest global idx in-thread
                atomicMin(sWin, ci);                           // smallest across block
            }
            __syncthreads();
            int w = *sWin;
            if (tid == (w & (FPS_T - 1))) {
                int i = w >> 9;
                sC[0] = px[i]; sC[1] = py[i]; sC[2] = pz[i];
                g_fps[b * NPOINT + t] = w;
            }
            __syncthreads();
        }
    } else {
        // ---------------- GEMM h = feat @ W^T (+ BN stats) ----------------
        int bid  = blockIdx.x - BATCH;
        int row0 = bid * 128;                      // rows over flattened [B*N, CIN]
        float* sf   = smem;                        // [128][65]
        float* sw   = smem + 128 * 65;             // [128][65]
        float* sSum = smem + 2 * 128 * 65;         // [128]
        float* sSq  = sSum + 128;                  // [128]
        if (tid < 128) { sSum[tid] = 0.f; sSq[tid] = 0.f; }
        const float* fsrc = feat + (size_t)row0 * CIN;
#pragma unroll
        for (int it = 0; it < 16; it++) {
            int e = it * 512 + tid;
            sf[(e >> 6) * 65 + (e & 63)] = fsrc[e];
            sw[(e >> 6) * 65 + (e & 63)] = Wm[e];
        }
        __syncthreads();
        int tx = tid & 31, ty = tid >> 5;
        float acc[8][4];
#pragma unroll
        for (int i = 0; i < 8; i++)
#pragma unroll
            for (int j = 0; j < 4; j++) acc[i][j] = 0.f;
#pragma unroll 8
        for (int k = 0; k < 64; k++) {
            float fr[8], wc[4];
#pragma unroll
            for (int i = 0; i < 8; i++) fr[i] = sf[(ty * 8 + i) * 65 + k];
#pragma unroll
            for (int j = 0; j < 4; j++) wc[j] = sw[(tx + 32 * j) * 65 + k];
#pragma unroll
            for (int i = 0; i < 8; i++)
#pragma unroll
                for (int j = 0; j < 4; j++)
                    acc[i][j] = fmaf(fr[i], wc[j], acc[i][j]);
        }
#pragma unroll
        for (int j = 0; j < 4; j++) {
            int c = tx + 32 * j;
            float s = 0.f, q = 0.f;
#pragma unroll
            for (int i = 0; i < 8; i++) {
                float v = acc[i][j];
                g_h[(size_t)(row0 + ty * 8 + i) * COUT + c] = v;
                s += v;
                q = fmaf(v, v, q);
            }
            atomicAdd(&sSum[c], s);
            atomicAdd(&sSq[c], q);
        }
        __syncthreads();
        if (tid < 128) {
            atomicAdd(&g_sum[tid], sSum[tid]);
            atomicAdd(&g_sq[tid],  sSq[tid]);
        }
    }
}

// ---------------- kernel 3: BN finalize ----------------
__global__ void bn_finalize_kernel(const float* __restrict__ gamma,
                                   const float* __restrict__ beta)
{
    int c = threadIdx.x;
    if (c < COUT) {
        float inv  = 1.f / (float)(BATCH * NPTS);
        float mean = g_sum[c] * inv;
        float var  = g_sq[c] * inv - mean * mean;
        float sc   = gamma[c] * rsqrtf(var + 1e-5f);
        g_scale[c] = sc;
        g_shift[c] = beta[c] - mean * sc;
    }
}

// ---------------- kernel 4: kNN (radix-histogram select) + max-pool ----------------
// One block = 2 queries of one batch. 256 threads.
#define CAP 1024

__global__ __launch_bounds__(256) void knn_pool_kernel(
    const float* __restrict__ xyz, float* __restrict__ out)
{
    extern __shared__ float smem[];
    float* dist0 = smem;                       // [8192]
    float* dist1 = smem + NPTS;                // [8192]
    int*   hist  = (int*)(smem + 2 * NPTS);    // [1024]
    int*   cand  = hist + 1024;                // [CAP]
    int*   nbr   = cand + CAP;                 // [2*16]
    int*   sCnt  = nbr + 32;                   // [1]
    int*   sBin  = sCnt + 1;                   // [1]
    float* sQ    = (float*)(sBin + 1);         // [6]

    int tid = threadIdx.x;
    int b   = blockIdx.y;
    int q0  = blockIdx.x * 2;
    const float* base = xyz + (size_t)b * NPTS * 3;

    if (tid == 0) {
        int f0 = g_fps[b * NPOINT + q0];
        int f1 = g_fps[b * NPOINT + q0 + 1];
        sQ[0] = base[f0 * 3]; sQ[1] = base[f0 * 3 + 1]; sQ[2] = base[f0 * 3 + 2];
        sQ[3] = base[f1 * 3]; sQ[4] = base[f1 * 3 + 1]; sQ[5] = base[f1 * 3 + 2];
    }
    __syncthreads();
    if (tid < 6) {  // new_xyz
        int qi = tid / 3, d = tid % 3;
        out[(size_t)(b * NPOINT + q0 + qi) * 3 + d] = sQ[tid];
    }
    float ax = sQ[0], ay = sQ[1], az = sQ[2];
    float bx = sQ[3], by = sQ[4], bz = sQ[5];
    for (int e = tid; e < NPTS; e += 256) {
        float x = base[e * 3], y = base[e * 3 + 1], z = base[e * 3 + 2];
        float dx = x - ax, dy = y - ay, dz = z - az;
        dist0[e] = fmaf(dx, dx, fmaf(dy, dy, dz * dz));
        dx = x - bx; dy = y - by; dz = z - bz;
        dist1[e] = fmaf(dx, dx, fmaf(dy, dy, dz * dz));
    }

    for (int qi = 0; qi < 2; qi++) {
        float* dst = qi ? dist1 : dist0;
        __syncthreads();
        for (int i = tid; i < 1024; i += 256) hist[i] = 0;
        if (tid == 0) *sCnt = 0;
        __syncthreads();
        for (int e = tid; e < NPTS; e += 256) {
            unsigned k = __float_as_uint(dst[e]);
            atomicAdd(&hist[k >> 21], 1);
        }
        __syncthreads();
        if (tid < 32) {   // find bin of 16th smallest (float bits monotone for d>=0)
            int cum = 0, found = -1;
            for (int ch = 0; ch < 32 && found < 0; ch++) {
                int v = hist[ch * 32 + tid];
                int s = v;
#pragma unroll
                for (int off = 1; off < 32; off <<= 1) {
                    int o = __shfl_up_sync(0xffffffffu, s, off);
                    if (tid >= off) s += o;
                }
                int tot = __shfl_sync(0xffffffffu, s, 31);
                unsigned m = __ballot_sync(0xffffffffu, cum + s >= KNN);
                if (m) found = ch * 32 + __ffs(m) - 1;
                cum += tot;
            }
            if (tid == 0) *sBin = found;
        }
        __syncthreads();
        int binStar = *sBin;
        for (int e = tid; e < NPTS; e += 256) {
            unsigned k = __float_as_uint(dst[e]);
            if ((int)(k >> 21) <= binStar) {
                int pos = atomicAdd(sCnt, 1);
                if (pos < CAP) cand[pos] = e;
            }
        }
        __syncthreads();
        int C = *sCnt;
        if (C <= CAP) {
            if (tid < 32) {   // exact top-16, tie -> lower index (matches top_k)
                for (int k = 0; k < KNN; k++) {
                    float bd = 1e30f; int bi = 0x7fffffff;
                    for (int ci = tid; ci < C; ci += 32) {
                        int e = cand[ci];
                        float d = dst[e];
                        if (d < bd || (d == bd && e < bi)) { bd = d; bi = e; }
                    }
#pragma unroll
                    for (int off = 16; off; off >>= 1) {
                        float od = __shfl_xor_sync(0xffffffffu, bd, off);
                        int   oi = __shfl_xor_sync(0xffffffffu, bi, off);
                        if (od < bd || (od == bd && oi < bi)) { bd = od; bi = oi; }
                    }
                    if (tid == 0) { nbr[qi * KNN + k] = bi; dst[bi] = 1e30f; }
                    __syncwarp();
                }
            }
        } else {
            // fallback (never expected): block-wide 16x argmin with marking
            float* rbd = (float*)hist;
            int*   rbi = cand;
            for (int k = 0; k < KNN; k++) {
                float bd = 1e30f; int bi = 0x7fffffff;
                for (int e = tid; e < NPTS; e += 256) {
                    float d = dst[e];
                    if (d < bd || (d == bd && e < bi)) { bd = d; bi = e; }
                }
#pragma unroll
                for (int off = 16; off; off >>= 1) {
                    float od = __shfl_xor_sync(0xffffffffu, bd, off);
                    int   oi = __shfl_xor_sync(0xffffffffu, bi, off);
                    if (od < bd || (od == bd && oi < bi)) { bd = od; bi = oi; }
                }
                if ((tid & 31) == 0) { rbd[tid >> 5] = bd; rbi[tid >> 5] = bi; }
                __syncthreads();
                if (tid == 0) {
                    for (int w = 1; w < 8; w++)
                        if (rbd[w] < bd || (rbd[w] == bd && rbi[w] < bi)) { bd = rbd[w]; bi = rbi[w]; }
                    nbr[qi * KNN + k] = bi;
                    dst[bi] = 1e30f;
                }
                __syncthreads();
            }
        }
    }
    __syncthreads();

    // ----- max-pool with fused affine+ReLU: thread = (query, channel) -----
    int qi = tid >> 7, c = tid & 127;
    float sc = g_scale[c], sh = g_shift[c];
    float m = -1e30f;
    const float* hb = g_h + (size_t)b * NPTS * COUT;
#pragma unroll
    for (int k = 0; k < KNN; k++) {
        int r = nbr[qi * KNN + k];
        float v = hb[(size_t)r * COUT + c];
        m = fmaxf(m, fmaf(v, sc, sh));
    }
    m = fmaxf(m, 0.f);  // ReLU commutes with the outer max
    out[(size_t)BATCH * NPOINT * 3 + (size_t)(b * NPOINT + q0 + qi) * COUT + c] = m;
}

// ---------------- launch ----------------
extern "C" void kernel_launch(void* const* d_in, const int* in_sizes, int n_in,
                              void* d_out, int out_size)
{
    const float* xyz   = (const float*)d_in[0];
    const float* feat  = (const float*)d_in[1];
    const float* Wm    = (const float*)d_in[2];
    // d_in[3] = bias: provably cancels in BN normalization -> unused
    const float* gamma = (const float*)d_in[4];
    const float* beta  = (const float*)d_in[5];
    float* out = (float*)d_out;

    const int FUSED_SMEM = (2 * 128 * 65 + 256) * sizeof(float);             // 67584
    const int KNN_SMEM   = (2 * NPTS + 1024 + CAP + 32 + 2 + 6) * sizeof(float); // 73888
    cudaFuncSetAttribute(fps_gemm_kernel, cudaFuncAttributeMaxDynamicSharedMemorySize, FUSED_SMEM);
    cudaFuncSetAttribute(knn_pool_kernel, cudaFuncAttributeMaxDynamicSharedMemorySize, KNN_SMEM);

    zero_kernel<<<1, 128>>>();
    fps_gemm_kernel<<<BATCH + (BATCH * NPTS / 128), 512, FUSED_SMEM>>>(xyz, feat, Wm);
    bn_finalize_kernel<<<1, 128>>>(gamma, beta);
    knn_pool_kernel<<<dim3(NPOINT / 2, BATCH), 256, KNN_SMEM>>>(xyz, out);
}

// round 2
// speedup vs baseline: 1.4810x; 1.4810x over previous
#include <cuda_runtime.h>
#include <cstdint>

#define BATCH   16
#define NPTS    8192
#define NPOINT  2048
#define KNN     16
#define CIN     64
#define COUT    128
#define CAP     512

#define GEMM_BLOCKS 1024
#define QPB 3
#define QBLK_PER_B ((NPOINT + QPB - 1) / QPB)        // 683
#define KNN_BLOCKS (BATCH * QBLK_PER_B)              // 10928
#define GRID (BATCH + GEMM_BLOCKS + KNN_BLOCKS)
#define SMEM_BYTES 126976
#define FEAT_OFF (BATCH * NPOINT * 3)

// ---------------- scratch ----------------
__device__ float    g_h[BATCH * NPTS * COUT];
__device__ int      g_fps[BATCH * NPOINT];
__device__ float    g_sum[COUT];
__device__ float    g_sq[COUT];
__device__ float    g_scale[COUT];
__device__ float    g_shift[COUT];
__device__ unsigned g_prog[BATCH];
__device__ unsigned g_done;
__device__ unsigned g_flag;

__global__ void zero_kernel() {
    int t = threadIdx.x;
    if (t < COUT) { g_sum[t] = 0.f; g_sq[t] = 0.f; }
    if (t < BATCH) g_prog[t] = 0u;
    if (t == 0) { g_done = 0u; g_flag = 0u; }
}

// ---------------- helpers ----------------
typedef unsigned long long ull;
__device__ __forceinline__ ull pk2(float a, float b) {
    ull r; asm("mov.b64 %0,{%1,%2};" : "=l"(r) : "f"(a), "f"(b)); return r;
}
__device__ __forceinline__ void up2(ull v, float& a, float& b) {
    asm("mov.b64 {%0,%1},%2;" : "=f"(a), "=f"(b) : "l"(v));
}
__device__ __forceinline__ ull add2(ull a, ull b) {
    ull r; asm("add.rn.f32x2 %0,%1,%2;" : "=l"(r) : "l"(a), "l"(b)); return r;
}
__device__ __forceinline__ ull mul2(ull a, ull b) {
    ull r; asm("mul.rn.f32x2 %0,%1,%2;" : "=l"(r) : "l"(a), "l"(b)); return r;
}
__device__ __forceinline__ ull fma2(ull a, ull b, ull c) {
    ull r; asm("fma.rn.f32x2 %0,%1,%2,%3;" : "=l"(r) : "l"(a), "l"(b), "l"(c)); return r;
}
__device__ __forceinline__ void st_rel(unsigned* p, unsigned v) {
    asm volatile("st.release.gpu.u32 [%0],%1;" :: "l"(p), "r"(v) : "memory");
}
__device__ __forceinline__ unsigned ld_acq(const unsigned* p) {
    unsigned v; asm volatile("ld.acquire.gpu.u32 %0,[%1];" : "=r"(v) : "l"(p) : "memory"); return v;
}

// ---------------- mega kernel ----------------
__global__ __launch_bounds__(512) void mega_kernel(
    const float* __restrict__ xyz,
    const float* __restrict__ feat,
    const float* __restrict__ Wm,
    const float* __restrict__ gamma,
    const float* __restrict__ beta,
    float* __restrict__ out)
{
    extern __shared__ float smem[];
    int tid = threadIdx.x;
    int bix = blockIdx.x;
    int lane = tid & 31, wid = tid >> 5;

    if (bix < BATCH) {
        // ================= FPS (one block per batch) =================
        int b = bix;
        const float* base = xyz + (size_t)b * NPTS * 3;
        float arr[48];
        {
            const float4* s4 = (const float4*)base + tid * 12;
            float4 v[12];
#pragma unroll
            for (int i = 0; i < 12; i++) v[i] = s4[i];
#pragma unroll
            for (int i = 0; i < 12; i++) {
                arr[i * 4 + 0] = v[i].x; arr[i * 4 + 1] = v[i].y;
                arr[i * 4 + 2] = v[i].z; arr[i * 4 + 3] = v[i].w;
            }
        }
        ull px[8], py[8], pz[8];
        float dist[16];
#pragma unroll
        for (int pr = 0; pr < 8; pr++) {
            px[pr] = pk2(arr[(2 * pr) * 3 + 0], arr[(2 * pr + 1) * 3 + 0]);
            py[pr] = pk2(arr[(2 * pr) * 3 + 1], arr[(2 * pr + 1) * 3 + 1]);
            pz[pr] = pk2(arr[(2 * pr) * 3 + 2], arr[(2 * pr + 1) * 3 + 2]);
        }
#pragma unroll
        for (int j = 0; j < 16; j++) dist[j] = 1e10f;

        float* sWarp = smem;                 // [16]
        int*   sWin  = (int*)(smem + 16);    // [2]
        if (tid == 0) {
            sWin[0] = 0x7fffffff; sWin[1] = 0x7fffffff;
            g_fps[b * NPOINT] = 0;
            st_rel(&g_prog[b], 1u);
        }
        float cx = __ldg(base + 0), cy = __ldg(base + 1), cz = __ldg(base + 2);
        __syncthreads();

        for (int t = 1; t < NPOINT; t++) {
            ull ncx = pk2(-cx, -cx), ncy = pk2(-cy, -cy), ncz = pk2(-cz, -cz);
            float lb = -1.f;
#pragma unroll
            for (int pr = 0; pr < 8; pr++) {
                ull dx = add2(px[pr], ncx);
                ull dy = add2(py[pr], ncy);
                ull dz = add2(pz[pr], ncz);
                ull tt = mul2(dz, dz);
                tt = fma2(dy, dy, tt);
                tt = fma2(dx, dx, tt);
                float d0, d1; up2(tt, d0, d1);
                dist[2 * pr]     = fminf(dist[2 * pr], d0);
                dist[2 * pr + 1] = fminf(dist[2 * pr + 1], d1);
                lb = fmaxf(lb, fmaxf(dist[2 * pr], dist[2 * pr + 1]));
            }
            unsigned wm = __reduce_max_sync(0xffffffffu, __float_as_uint(lb));
            if (lane == 0) sWarp[wid] = __uint_as_float(wm);
            if (tid == 0) sWin[t & 1] = 0x7fffffff;
            __syncthreads();
            float gv = sWarp[lane & 15];
            float gb = __uint_as_float(__reduce_max_sync(0xffffffffu, __float_as_uint(gv)));
            if (lb == gb) {
                int ci = 0x7fffffff;
#pragma unroll
                for (int j = 15; j >= 0; j--)
                    if (dist[j] == gb) ci = tid * 16 + j;
                atomicMin(&sWin[t & 1], ci);
            }
            __syncthreads();
            int w = sWin[t & 1];
            if (tid == 0) {
                g_fps[b * NPOINT + t] = w;
                st_rel(&g_prog[b], (unsigned)(t + 1));
            }
            cx = __ldg(base + w * 3 + 0);
            cy = __ldg(base + w * 3 + 1);
            cz = __ldg(base + w * 3 + 2);
        }
    } else if (bix < BATCH + GEMM_BLOCKS) {
        // ================= GEMM h = feat @ W^T + BN stats =================
        int bid  = bix - BATCH;
        int row0 = bid * 128;
        float* sf   = smem;                    // [128][65]
        float* sw   = smem + 128 * 65;         // [128][65]
        float* sSum = smem + 2 * 128 * 65;     // [128]
        float* sSq  = sSum + 128;              // [128]
        if (tid < 128) { sSum[tid] = 0.f; sSq[tid] = 0.f; }
        const float* fsrc = feat + (size_t)row0 * CIN;
#pragma unroll
        for (int it = 0; it < 16; it++) {
            int e = it * 512 + tid;
            sf[(e >> 6) * 65 + (e & 63)] = fsrc[e];
            sw[(e >> 6) * 65 + (e & 63)] = Wm[e];
        }
        __syncthreads();
        int tx = tid & 31, ty = tid >> 5;
        float acc[8][4];
#pragma unroll
        for (int i = 0; i < 8; i++)
#pragma unroll
            for (int j = 0; j < 4; j++) acc[i][j] = 0.f;
#pragma unroll 8
        for (int k = 0; k < 64; k++) {
            float fr[8], wc[4];
#pragma unroll
            for (int i = 0; i < 8; i++) fr[i] = sf[(ty * 8 + i) * 65 + k];
#pragma unroll
            for (int j = 0; j < 4; j++) wc[j] = sw[(tx + 32 * j) * 65 + k];
#pragma unroll
            for (int i = 0; i < 8; i++)
#pragma unroll
                for (int j = 0; j < 4; j++)
                    acc[i][j] = fmaf(fr[i], wc[j], acc[i][j]);
        }
#pragma unroll
        for (int j = 0; j < 4; j++) {
            int c = tx + 32 * j;
            float s = 0.f, q = 0.f;
#pragma unroll
            for (int i = 0; i < 8; i++) {
                float v = acc[i][j];
                g_h[(size_t)(row0 + ty * 8 + i) * COUT + c] = v;
                s += v;
                q = fmaf(v, v, q);
            }
            atomicAdd(&sSum[c], s);
            atomicAdd(&sSq[c], q);
        }
        __syncthreads();
        if (tid < 128) {
            atomicAdd(&g_sum[tid], sSum[tid]);
            atomicAdd(&g_sq[tid],  sSq[tid]);
        }
        __syncthreads();
        if (tid == 0) {
            __threadfence();
            unsigned o = atomicAdd(&g_done, 1u);
            if (o == GEMM_BLOCKS - 1) {
                __threadfence();
                float inv = 1.f / (float)(BATCH * NPTS);
                for (int c = 0; c < COUT; c++) {
                    float mean = g_sum[c] * inv;
                    float var  = g_sq[c] * inv - mean * mean;
                    float sc   = gamma[c] * rsqrtf(var + 1e-5f);
                    g_scale[c] = sc;
                    g_shift[c] = beta[c] - mean * sc;
                }
                __threadfence();
                st_rel(&g_flag, 1u);
            }
        }
    } else {
        // ================= kNN + max-pool (3 queries/block) =================
        int kb   = bix - BATCH - GEMM_BLOCKS;
        int b    = kb & 15;
        int qblk = kb >> 4;
        int q0   = qblk * QPB;
        int nq   = NPOINT - q0 < QPB ? NPOINT - q0 : QPB;
        const float* base = xyz + (size_t)b * NPTS * 3;

        float* d0 = smem;
        float* d1 = smem + NPTS;
        float* d2 = smem + 2 * NPTS;
        int*   hist  = (int*)(smem + 3 * NPTS);     // [3][1024]
        unsigned* candB = (unsigned*)(hist + 3 * 1024); // [3][CAP]
        int*   candI = (int*)(candB + 3 * CAP);     // [3][CAP]
        int*   cnt   = candI + 3 * CAP;             // [3]
        int*   sBin  = cnt + 3;                     // [3]
        int*   ovf   = sBin + 3;                    // [3]
        int*   sFid  = ovf + 3;                     // [3]
        int*   nbr   = sFid + 3;                    // [48]

        for (int i = tid; i < 3 * 1024; i += 512) hist[i] = 0;
        if (tid < 3) { cnt[tid] = 0; ovf[tid] = 0; }
        if (tid == 0) {
            unsigned need = (unsigned)(q0 + nq);
            while (ld_acq(&g_prog[b]) < need) __nanosleep(200);
            for (int q = 0; q < nq; q++) sFid[q] = g_fps[b * NPOINT + q0 + q];
            for (int q = nq; q < 3; q++) sFid[q] = sFid[0];
        }
        __syncthreads();

        float qx[3], qy[3], qz[3];
#pragma unroll
        for (int q = 0; q < 3; q++) {
            int f = sFid[q];
            qx[q] = __ldg(base + f * 3 + 0);
            qy[q] = __ldg(base + f * 3 + 1);
            qz[q] = __ldg(base + f * 3 + 2);
        }
        if (tid < 9) {
            int qi = tid / 3, dd = tid % 3;
            if (qi < nq)
                out[(size_t)(b * NPOINT + q0 + qi) * 3 + dd] =
                    __ldg(base + sFid[qi] * 3 + dd);
        }

        // pass 1: distances (+ subsample histogram on first 1024 elements)
        float* dq[3] = { d0, d1, d2 };
#pragma unroll 1
        for (int it = 0; it < 16; it++) {
            int e = it * 512 + tid;
            float x = base[e * 3], y = base[e * 3 + 1], z = base[e * 3 + 2];
#pragma unroll
            for (int q = 0; q < 3; q++) {
                float dx = x - qx[q], dy = y - qy[q], dz = z - qz[q];
                float d = fmaf(dx, dx, fmaf(dy, dy, dz * dz));
                dq[q][e] = d;
                if (it < 2 && q < nq)
                    atomicAdd(&hist[q * 1024 + (int)(__float_as_uint(d) >> 21)], 1);
            }
        }
        __syncthreads();

        // find bin of 16th-smallest subsample value (warp q)
        if (wid < 3 && wid < nq) {
            int q = wid;
            int cum = 0, found = -1;
            for (int ch = 0; ch < 32 && found < 0; ch++) {
                int v = hist[q * 1024 + ch * 32 + lane];
                int s = v;
#pragma unroll
                for (int off = 1; off < 32; off <<= 1) {
                    int o = __shfl_up_sync(0xffffffffu, s, off);
                    if (lane >= off) s += o;
                }
                int tot = __shfl_sync(0xffffffffu, s, 31);
                unsigned m = __ballot_sync(0xffffffffu, cum + s >= KNN);
                if (m) found = ch * 32 + __ffs(m) - 1;
                cum += tot;
            }
            if (lane == 0) sBin[q] = found;
        }
        __syncthreads();

        // candidate collection
        int b0 = sBin[0], b1 = sBin[1], b2 = sBin[2];
#pragma unroll 1
        for (int it = 0; it < 16; it++) {
            int e = it * 512 + tid;
            unsigned k0 = __float_as_uint(d0[e]);
            unsigned k1 = __float_as_uint(d1[e]);
            unsigned k2 = __float_as_uint(d2[e]);
            if ((int)(k0 >> 21) <= b0) {
                int p = atomicAdd(&cnt[0], 1);
                if (p < CAP) { candB[p] = k0; candI[p] = e; } else ovf[0] = 1;
            }
            if (nq > 1 && (int)(k1 >> 21) <= b1) {
                int p = atomicAdd(&cnt[1], 1);
                if (p < CAP) { candB[CAP + p] = k1; candI[CAP + p] = e; } else ovf[1] = 1;
            }
            if (nq > 2 && (int)(k2 >> 21) <= b2) {
                int p = atomicAdd(&cnt[2], 1);
                if (p < CAP) { candB[2 * CAP + p] = k2; candI[2 * CAP + p] = e; } else ovf[2] = 1;
            }
        }
        __syncthreads();

        // selection: warp q extracts exact top-16 (tie -> lower index)
        if (wid < 3 && wid < nq) {
            int q = wid;
            if (!ovf[q]) {
                int C = cnt[q]; if (C > CAP) C = CAP;
                unsigned* cb = candB + q * CAP;
                int* ci_ = candI + q * CAP;
                for (int k = 0; k < KNN; k++) {
                    unsigned mb = 0xFFFFFFFFu; int mi = 0x7fffffff, ms = -1;
                    for (int s = lane; s < C; s += 32) {
                        unsigned bb = cb[s];
                        if (bb < mb) { mb = bb; mi = ci_[s]; ms = s; }
                        else if (bb == mb) { int ii = ci_[s]; if (ii < mi) { mi = ii; ms = s; } }
                    }
                    unsigned g  = __reduce_min_sync(0xffffffffu, mb);
                    unsigned cc = (mb == g) ? (unsigned)mi : 0xffffffffu;
                    unsigned gi = __reduce_min_sync(0xffffffffu, cc);
                    if (mb == g && (unsigned)mi == gi) cb[ms] = 0xFFFFFFFFu;
                    if (lane == 0) nbr[q * KNN + k] = (int)gi;
                    __syncwarp();
                }
            } else {
                float* dd = dq[q];
                for (int k = 0; k < KNN; k++) {
                    unsigned mb = 0xFFFFFFFFu; int mi = 0x7fffffff;
                    for (int e = lane; e < NPTS; e += 32) {
                        unsigned bb = __float_as_uint(dd[e]);
                        if (bb < mb || (bb == mb && e < mi)) { mb = bb; mi = e; }
                    }
                    unsigned g  = __reduce_min_sync(0xffffffffu, mb);
                    unsigned cc = (mb == g) ? (unsigned)mi : 0xffffffffu;
                    unsigned gi = __reduce_min_sync(0xffffffffu, cc);
                    if (lane == 0) nbr[q * KNN + k] = (int)gi;
                    __syncwarp();
                    dd[gi] = __uint_as_float(0x7f000000u);
                    __syncwarp();
                }
            }
        }
        __syncthreads();

        // wait for BN stats, then pooled output
        if (tid == 0) {
            while (ld_acq(&g_flag) == 0u) __nanosleep(200);
        }
        __syncthreads();

        int g = tid >> 7, c = tid & 127;
        if (g < nq) {
            float sc = g_scale[c], sh = g_shift[c];
            float m = -1e30f;
            const float* hb = g_h + (size_t)b * NPTS * COUT;
#pragma unroll
            for (int k = 0; k < KNN; k++) {
                int r = nbr[g * KNN + k];
                float v = hb[(size_t)r * COUT + c];
                m = fmaxf(m, fmaf(v, sc, sh));
            }
            m = fmaxf(m, 0.f);
            out[FEAT_OFF + (size_t)(b * NPOINT + q0 + g) * COUT + c] = m;
        }
    }
}

// ---------------- launch ----------------
extern "C" void kernel_launch(void* const* d_in, const int* in_sizes, int n_in,
                              void* d_out, int out_size)
{
    const float* xyz   = (const float*)d_in[0];
    const float* feat  = (const float*)d_in[1];
    const float* Wm    = (const float*)d_in[2];
    // d_in[3] = bias: cancels inside BatchNorm -> unused
    const float* gamma = (const float*)d_in[4];
    const float* beta  = (const float*)d_in[5];
    float* out = (float*)d_out;

    cudaFuncSetAttribute(mega_kernel, cudaFuncAttributeMaxDynamicSharedMemorySize, SMEM_BYTES);
    zero_kernel<<<1, 128>>>();
    mega_kernel<<<GRID, 512, SMEM_BYTES>>>(xyz, feat, Wm, gamma, beta, out);
}

// round 3
// speedup vs baseline: 1.6494x; 1.1137x over previous
#include <cuda_runtime.h>
#include <cstdint>

#define BATCH   16
#define NPTS    8192
#define NPOINT  2048
#define KNN     16
#define CIN     64
#define COUT    128
#define CAP     384
#define QPB     8

#define GEMM_BLOCKS 1024
#define KNN_BLOCKS  (BATCH * (NPOINT / QPB))           // 4096
#define GRID        (BATCH + GEMM_BLOCKS + KNN_BLOCKS) // 5136
#define FEAT_OFF    (BATCH * NPOINT * 3)
#define SMEM_BYTES  ((3 * NPTS + 64) * 4)              // 98560

// ---------------- scratch ----------------
__device__ __align__(16) float g_h[BATCH * NPTS * COUT];
__device__ int      g_fps[BATCH * NPOINT];
__device__ float    g_sum[COUT];
__device__ float    g_sq[COUT];
__device__ __align__(16) float g_scale[COUT];
__device__ __align__(16) float g_shift[COUT];
__device__ unsigned g_prog[BATCH];
__device__ unsigned g_done;
__device__ unsigned g_flag;

__global__ void zero_kernel() {
    int t = threadIdx.x;
    if (t < COUT) { g_sum[t] = 0.f; g_sq[t] = 0.f; }
    if (t < BATCH) g_prog[t] = 0u;
    if (t == 0) { g_done = 0u; g_flag = 0u; }
}

// ---------------- helpers ----------------
typedef unsigned long long ull;
__device__ __forceinline__ ull pk2(float a, float b) {
    ull r; asm("mov.b64 %0,{%1,%2};" : "=l"(r) : "f"(a), "f"(b)); return r;
}
__device__ __forceinline__ void up2(ull v, float& a, float& b) {
    asm("mov.b64 {%0,%1},%2;" : "=f"(a), "=f"(b) : "l"(v));
}
__device__ __forceinline__ ull add2(ull a, ull b) {
    ull r; asm("add.rn.f32x2 %0,%1,%2;" : "=l"(r) : "l"(a), "l"(b)); return r;
}
__device__ __forceinline__ ull mul2(ull a, ull b) {
    ull r; asm("mul.rn.f32x2 %0,%1,%2;" : "=l"(r) : "l"(a), "l"(b)); return r;
}
__device__ __forceinline__ ull fma2(ull a, ull b, ull c) {
    ull r; asm("fma.rn.f32x2 %0,%1,%2,%3;" : "=l"(r) : "l"(a), "l"(b), "l"(c)); return r;
}
__device__ __forceinline__ void st_rel(unsigned* p, unsigned v) {
    asm volatile("st.release.gpu.u32 [%0],%1;" :: "l"(p), "r"(v) : "memory");
}
__device__ __forceinline__ unsigned ld_acq(const unsigned* p) {
    unsigned v; asm volatile("ld.acquire.gpu.u32 %0,[%1];" : "=r"(v) : "l"(p) : "memory"); return v;
}

// ---------------- mega kernel ----------------
__global__ __launch_bounds__(512) void mega_kernel(
    const float* __restrict__ xyz,
    const float* __restrict__ feat,
    const float* __restrict__ Wm,
    const float* __restrict__ gamma,
    const float* __restrict__ beta,
    float* __restrict__ out)
{
    extern __shared__ float smem[];
    int tid = threadIdx.x;
    int bix = blockIdx.x;
    int lane = tid & 31, wid = tid >> 5;

    if (bix < BATCH) {
        // ================= FPS: one block per batch, xyz staged in smem =================
        int b = bix;
        const float* base = xyz + (size_t)b * NPTS * 3;
        float arr[48];
        {
            const float4* s4 = (const float4*)base + tid * 12;
            float4 v[12];
#pragma unroll
            for (int i = 0; i < 12; i++) v[i] = s4[i];
#pragma unroll
            for (int i = 0; i < 12; i++) {
                arr[i * 4 + 0] = v[i].x; arr[i * 4 + 1] = v[i].y;
                arr[i * 4 + 2] = v[i].z; arr[i * 4 + 3] = v[i].w;
            }
        }
        float* sx = smem;
        float* sy = smem + NPTS;
        float* sz = smem + 2 * NPTS;
        unsigned* usWarp = (unsigned*)(smem + 3 * NPTS);  // [16]
        int*      sWin   = (int*)(smem + 3 * NPTS + 16);  // [2]
#pragma unroll
        for (int j = 0; j < 16; j++) {
            int p = tid * 16 + j;
            sx[p] = arr[3 * j + 0];
            sy[p] = arr[3 * j + 1];
            sz[p] = arr[3 * j + 2];
        }
        ull px[8], py[8], pz[8];
        float dist[16];
#pragma unroll
        for (int pr = 0; pr < 8; pr++) {
            px[pr] = pk2(arr[(2 * pr) * 3 + 0], arr[(2 * pr + 1) * 3 + 0]);
            py[pr] = pk2(arr[(2 * pr) * 3 + 1], arr[(2 * pr + 1) * 3 + 1]);
            pz[pr] = pk2(arr[(2 * pr) * 3 + 2], arr[(2 * pr + 1) * 3 + 2]);
        }
#pragma unroll
        for (int j = 0; j < 16; j++) dist[j] = 1e10f;
        if (tid == 0) {
            sWin[0] = 0x7fffffff; sWin[1] = 0x7fffffff;
            g_fps[b * NPOINT] = 0;
            st_rel(&g_prog[b], 1u);
        }
        __syncthreads();
        float cx = sx[0], cy = sy[0], cz = sz[0];

        for (int t = 1; t < NPOINT; t++) {
            ull ncx = pk2(-cx, -cx), ncy = pk2(-cy, -cy), ncz = pk2(-cz, -cz);
            float lb = -1.f;
#pragma unroll
            for (int pr = 0; pr < 8; pr++) {
                ull dx = add2(px[pr], ncx);
                ull dy = add2(py[pr], ncy);
                ull dz = add2(pz[pr], ncz);
                ull tt = mul2(dz, dz);
                tt = fma2(dy, dy, tt);
                tt = fma2(dx, dx, tt);
                float d0, d1; up2(tt, d0, d1);
                dist[2 * pr]     = fminf(dist[2 * pr], d0);
                dist[2 * pr + 1] = fminf(dist[2 * pr + 1], d1);
                lb = fmaxf(lb, fmaxf(dist[2 * pr], dist[2 * pr + 1]));
            }
            unsigned wm = __reduce_max_sync(0xffffffffu, __float_as_uint(lb));
            if (lane == 0) usWarp[wid] = wm;
            if (tid == 0) sWin[(t + 1) & 1] = 0x7fffffff;   // prep next parity
            __syncthreads();
            unsigned gvb = usWarp[lane & 15];
            unsigned gbb = __reduce_max_sync(0xffffffffu, gvb);
            float gb = __uint_as_float(gbb);
            if (lb == gb) {
                unsigned m = 0;
#pragma unroll
                for (int j = 0; j < 16; j++)
                    if (dist[j] == gb) m |= (1u << j);
                if (m) atomicMin(&sWin[t & 1], (tid << 4) + (__ffs(m) - 1));
            }
            __syncthreads();
            int w = sWin[t & 1];
            if (tid == 0) {
                g_fps[b * NPOINT + t] = w;
                st_rel(&g_prog[b], (unsigned)(t + 1));
            }
            cx = sx[w]; cy = sy[w]; cz = sz[w];
        }
    } else if (bix < BATCH + GEMM_BLOCKS) {
        // ================= GEMM h = feat @ W^T + BN stats =================
        int bid  = bix - BATCH;
        int row0 = bid * 128;
        float* sf   = smem;                    // [128][65]
        float* sw   = smem + 128 * 65;         // [128][65]
        float* sSum = smem + 2 * 128 * 65;     // [128]
        float* sSq  = sSum + 128;              // [128]
        int*   sLast = (int*)(sSq + 128);      // [1]
        if (tid < 128) { sSum[tid] = 0.f; sSq[tid] = 0.f; }
        const float* fsrc = feat + (size_t)row0 * CIN;
#pragma unroll
        for (int it = 0; it < 16; it++) {
            int e = it * 512 + tid;
            sf[(e >> 6) * 65 + (e & 63)] = fsrc[e];
            sw[(e >> 6) * 65 + (e & 63)] = Wm[e];
        }
        __syncthreads();
        int tx = tid & 31, ty = tid >> 5;
        float acc[8][4];
#pragma unroll
        for (int i = 0; i < 8; i++)
#pragma unroll
            for (int j = 0; j < 4; j++) acc[i][j] = 0.f;
#pragma unroll 8
        for (int k = 0; k < 64; k++) {
            float fr[8], wc[4];
#pragma unroll
            for (int i = 0; i < 8; i++) fr[i] = sf[(ty * 8 + i) * 65 + k];
#pragma unroll
            for (int j = 0; j < 4; j++) wc[j] = sw[(tx + 32 * j) * 65 + k];
#pragma unroll
            for (int i = 0; i < 8; i++)
#pragma unroll
                for (int j = 0; j < 4; j++)
                    acc[i][j] = fmaf(fr[i], wc[j], acc[i][j]);
        }
#pragma unroll
        for (int j = 0; j < 4; j++) {
            int c = tx + 32 * j;
            float s = 0.f, q = 0.f;
#pragma unroll
            for (int i = 0; i < 8; i++) {
                float v = acc[i][j];
                g_h[(size_t)(row0 + ty * 8 + i) * COUT + c] = v;
                s += v;
                q = fmaf(v, v, q);
            }
            atomicAdd(&sSum[c], s);
            atomicAdd(&sSq[c], q);
        }
        __syncthreads();
        if (tid < 128) {
            atomicAdd(&g_sum[tid], sSum[tid]);
            atomicAdd(&g_sq[tid],  sSq[tid]);
        }
        __syncthreads();
        if (tid == 0) {
            __threadfence();
            unsigned o = atomicAdd(&g_done, 1u);
            *sLast = (o == GEMM_BLOCKS - 1) ? 1 : 0;
        }
        __syncthreads();
        if (*sLast) {
            if (tid < COUT) {
                __threadfence();
                int c = tid;
                float inv  = 1.f / (float)(BATCH * NPTS);
                float mean = g_sum[c] * inv;
                float var  = g_sq[c] * inv - mean * mean;
                float sc   = gamma[c] * rsqrtf(var + 1e-5f);
                g_scale[c] = sc;
                g_shift[c] = beta[c] - mean * sc;
            }
            __syncthreads();
            if (tid == 0) { __threadfence(); st_rel(&g_flag, 1u); }
        }
    } else {
        // ================= kNN + max-pool: 8 queries/block, points in registers =================
        int kb   = bix - BATCH - GEMM_BLOCKS;
        int b    = kb & 15;
        int qblk = kb >> 4;
        int q0   = qblk * QPB;
        const float* base = xyz + (size_t)b * NPTS * 3;

        int*      hist  = (int*)smem;                         // [1024]
        unsigned* candB = (unsigned*)(smem + 1024);           // [8][CAP]
        int*      candI = (int*)(smem + 1024 + 8 * CAP);      // [8][CAP]
        float*    sDist = smem + 1024 + 16 * CAP;             // [8192] fallback
        float4*   sPool = (float4*)(smem + 1024 + 16 * CAP + NPTS); // [8][32]
        float*    tail  = smem + 1024 + 16 * CAP + NPTS + 1024;
        float*    sQ    = tail;                 // [24]
        int*      nbr   = (int*)(tail + 24);    // [128]
        int*      cnt   = (int*)(tail + 152);   // [8]
        int*      ovf   = (int*)(tail + 160);   // [8]
        int*      sBin  = (int*)(tail + 168);   // [8]
        int*      sFid  = (int*)(tail + 176);   // [8]
        ull*      sKey  = (ull*)(tail + 184);   // [1] (8B aligned: even float idx)

        // coords into registers
        float arr[48];
        {
            const float4* s4 = (const float4*)base + tid * 12;
            float4 v[12];
#pragma unroll
            for (int i = 0; i < 12; i++) v[i] = s4[i];
#pragma unroll
            for (int i = 0; i < 12; i++) {
                arr[i * 4 + 0] = v[i].x; arr[i * 4 + 1] = v[i].y;
                arr[i * 4 + 2] = v[i].z; arr[i * 4 + 3] = v[i].w;
            }
        }
        ull px[8], py[8], pz[8];
#pragma unroll
        for (int pr = 0; pr < 8; pr++) {
            px[pr] = pk2(arr[(2 * pr) * 3 + 0], arr[(2 * pr + 1) * 3 + 0]);
            py[pr] = pk2(arr[(2 * pr) * 3 + 1], arr[(2 * pr + 1) * 3 + 1]);
            pz[pr] = pk2(arr[(2 * pr) * 3 + 2], arr[(2 * pr + 1) * 3 + 2]);
        }

        if (tid < 8) { cnt[tid] = 0; ovf[tid] = 0; }
        if (tid == 0) {
            unsigned need = (unsigned)(q0 + QPB);
            while (ld_acq(&g_prog[b]) < need) __nanosleep(200);
            for (int q = 0; q < QPB; q++) sFid[q] = g_fps[b * NPOINT + q0 + q];
        }
        __syncthreads();
        if (tid < 24) {
            int q = tid / 3, d = tid % 3;
            float vv = __ldg(base + sFid[q] * 3 + d);
            sQ[q * 3 + d] = vv;
            out[(size_t)(b * NPOINT + q0 + q) * 3 + d] = vv;
        }

        float dq[16];
        for (int q = 0; q < QPB; q++) {
            for (int i = tid; i < 1024; i += 512) hist[i] = 0;
            __syncthreads();
            float cxq = sQ[3 * q], cyq = sQ[3 * q + 1], czq = sQ[3 * q + 2];
            ull ncx = pk2(-cxq, -cxq), ncy = pk2(-cyq, -cyq), ncz = pk2(-czq, -czq);
#pragma unroll
            for (int pr = 0; pr < 8; pr++) {
                ull dx = add2(px[pr], ncx);
                ull dy = add2(py[pr], ncy);
                ull dz = add2(pz[pr], ncz);
                ull tt = mul2(dz, dz);
                tt = fma2(dy, dy, tt);
                tt = fma2(dx, dx, tt);
                up2(tt, dq[2 * pr], dq[2 * pr + 1]);
            }
            atomicAdd(&hist[__float_as_uint(dq[0]) >> 21], 1);
            atomicAdd(&hist[__float_as_uint(dq[8]) >> 21], 1);
            __syncthreads();
            if (wid == 0) {   // bin of 16th-smallest subsample value
                int cum = 0, found = -1;
                for (int ch = 0; ch < 32 && found < 0; ch++) {
                    int v = hist[ch * 32 + lane];
                    int s = v;
#pragma unroll
                    for (int off = 1; off < 32; off <<= 1) {
                        int o = __shfl_up_sync(0xffffffffu, s, off);
                        if (lane >= off) s += o;
                    }
                    int tot = __shfl_sync(0xffffffffu, s, 31);
                    unsigned m = __ballot_sync(0xffffffffu, cum + s >= KNN);
                    if (m) found = ch * 32 + __ffs(m) - 1;
                    cum += tot;
                }
                if (lane == 0) sBin[q] = found;
            }
            __syncthreads();
            int bs = sBin[q];
#pragma unroll
            for (int j = 0; j < 16; j++) {
                unsigned bits = __float_as_uint(dq[j]);
                if ((int)(bits >> 21) <= bs) {
                    int pos = atomicAdd(&cnt[q], 1);
                    if (pos < CAP) {
                        candB[q * CAP + pos] = bits;
                        candI[q * CAP + pos] = (tid << 4) + j;
                    } else ovf[q] = 1;
                }
            }
        }
        __syncthreads();

        // parallel selection: warp q handles query q
        if (wid < QPB) {
            int q = wid;
            if (!ovf[q]) {
                int C = cnt[q]; if (C > CAP) C = CAP;
                unsigned* cb = candB + q * CAP;
                int* ci_ = candI + q * CAP;
                for (int k = 0; k < KNN; k++) {
                    unsigned mb = 0xFFFFFFFFu; int mi = 0x7fffffff, ms = -1;
                    for (int s = lane; s < C; s += 32) {
                        unsigned bb = cb[s];
                        if (bb < mb) { mb = bb; mi = ci_[s]; ms = s; }
                        else if (bb == mb) { int ii = ci_[s]; if (ii < mi) { mi = ii; ms = s; } }
                    }
                    unsigned g  = __reduce_min_sync(0xffffffffu, mb);
                    unsigned cc = (mb == g) ? (unsigned)mi : 0xffffffffu;
                    unsigned gi = __reduce_min_sync(0xffffffffu, cc);
                    if (mb == g && (unsigned)mi == gi) cb[ms] = 0xFFFFFFFFu;
                    if (lane == 0) nbr[q * KNN + k] = (int)gi;
                    __syncwarp();
                }
            }
        }
        __syncthreads();

        // rare fallback: exact block-wide selection with recomputed distances
        for (int q = 0; q < QPB; q++) {
            if (!ovf[q]) continue;
            float cxq = sQ[3 * q], cyq = sQ[3 * q + 1], czq = sQ[3 * q + 2];
            ull ncx = pk2(-cxq, -cxq), ncy = pk2(-cyq, -cyq), ncz = pk2(-czq, -czq);
#pragma unroll
            for (int pr = 0; pr < 8; pr++) {
                ull dx = add2(px[pr], ncx);
                ull dy = add2(py[pr], ncy);
                ull dz = add2(pz[pr], ncz);
                ull tt = mul2(dz, dz);
                tt = fma2(dy, dy, tt);
                tt = fma2(dx, dx, tt);
                float d0, d1; up2(tt, d0, d1);
                sDist[(tid << 4) + 2 * pr] = d0;
                sDist[(tid << 4) + 2 * pr + 1] = d1;
            }
            __syncthreads();
            for (int k = 0; k < KNN; k++) {
                if (tid == 0) *sKey = ~0ull;
                __syncthreads();
                ull best = ~0ull;
#pragma unroll
                for (int j = 0; j < 16; j++) {
                    int p = (tid << 4) + j;
                    ull kk = ((ull)__float_as_uint(sDist[p]) << 32) | (unsigned)p;
                    if (kk < best) best = kk;
                }
                atomicMin(sKey, best);
                __syncthreads();
                int g = (int)(*sKey & 0xffffffffu);
                if (tid == 0) nbr[q * KNN + k] = g;
                if ((g >> 4) == tid) sDist[g] = __uint_as_float(0x7f000000u);
                __syncthreads();
            }
        }

        // wait for BN scale/shift
        if (tid == 0) { while (ld_acq(&g_flag) == 0u) __nanosleep(200); }
        __syncthreads();

        // max-pool: 64 threads/query, float4 channels, two row-halves
        {
            int q  = tid >> 6;
            int c4 = tid & 31;
            int rh = (tid >> 5) & 1;
            const float4* hb4 = (const float4*)g_h + (size_t)b * NPTS * 32;
            float4 sc = ((const float4*)g_scale)[c4];
            float4 sh = ((const float4*)g_shift)[c4];
            float4 m = make_float4(-1e30f, -1e30f, -1e30f, -1e30f);
#pragma unroll
            for (int i = 0; i < 8; i++) {
                int r = nbr[q * KNN + rh * 8 + i];
                float4 v = __ldg(&hb4[(size_t)r * 32 + c4]);
                m.x = fmaxf(m.x, fmaf(v.x, sc.x, sh.x));
                m.y = fmaxf(m.y, fmaf(v.y, sc.y, sh.y));
                m.z = fmaxf(m.z, fmaf(v.z, sc.z, sh.z));
                m.w = fmaxf(m.w, fmaf(v.w, sc.w, sh.w));
            }
            if (rh == 1) sPool[q * 32 + c4] = m;
            __syncthreads();
            if (rh == 0) {
                float4 o = sPool[q * 32 + c4];
                m.x = fmaxf(fmaxf(m.x, o.x), 0.f);
                m.y = fmaxf(fmaxf(m.y, o.y), 0.f);
                m.z = fmaxf(fmaxf(m.z, o.z), 0.f);
                m.w = fmaxf(fmaxf(m.w, o.w), 0.f);
                float4* out4 = (float4*)(out + FEAT_OFF);
                out4[(size_t)(b * NPOINT + q0 + q) * 32 + c4] = m;
            }
        }
    }
}

// ---------------- launch ----------------
extern "C" void kernel_launch(void* const* d_in, const int* in_sizes, int n_in,
                              void* d_out, int out_size)
{
    const float* xyz   = (const float*)d_in[0];
    const float* feat  = (const float*)d_in[1];
    const float* Wm    = (const float*)d_in[2];
    // d_in[3] = bias: cancels inside BatchNorm -> unused
    const float* gamma = (const float*)d_in[4];
    const float* beta  = (const float*)d_in[5];
    float* out = (float*)d_out;

    cudaFuncSetAttribute(mega_kernel, cudaFuncAttributeMaxDynamicSharedMemorySize, SMEM_BYTES);
    zero_kernel<<<1, 128>>>();
    mega_kernel<<<GRID, 512, SMEM_BYTES>>>(xyz, feat, Wm, gamma, beta, out);
}